// round 7
// baseline (speedup 1.0000x reference)
#include <cuda_runtime.h>
#include <cuda_fp16.h>
#include <cstdint>

#define NN 5000
#define KP 5120      // padded K/M dim (multiple of 256)
#define JJ 4096      // B*C
#define DD 10
#define CC 64

// ---- device-global scratch (allocation-free rule) ----
static __device__ __align__(16) __half g_sh[(size_t)KP * KP]; // support fp16 [n][m]
static __device__ __align__(16) __half g_xh[(size_t)JJ * KP]; // X fp16 [j][k] = x[b][k][c]
static __device__ float g_y1[(size_t)NN * JJ];                 // support @ X  [n][j]
static __device__ float g_et[DD * NN];
static __device__ float g_rinv[NN];

// ================= small prep kernels =================
__global__ void k_transpose_e(const float* __restrict__ E) {
    int n = blockIdx.x * 256 + threadIdx.x;
    if (n < NN) {
#pragma unroll
        for (int d = 0; d < DD; d++) g_et[d * NN + n] = E[n * DD + d];
    }
}

__global__ void k_rowsum() {
    __shared__ float se[DD];
    __shared__ float sred[256];
    int n = blockIdx.x, t = threadIdx.x;
    if (t < DD) se[t] = g_et[t * NN + n];
    __syncthreads();
    float s = 0.f;
    for (int m = t; m < NN; m += 256) {
        float dot = 0.f;
#pragma unroll
        for (int d = 0; d < DD; d++) dot += se[d] * g_et[d * NN + m];
        s += __expf(fmaxf(dot, 0.f));
    }
    sred[t] = s;
    __syncthreads();
    for (int off = 128; off > 0; off >>= 1) {
        if (t < off) sred[t] += sred[t + off];
        __syncthreads();
    }
    if (t == 0) g_rinv[n] = 1.f / sred[0];
}

// support -> fp16, padded to KP x KP (zeros outside 5000x5000)
__global__ void k_support(const float* __restrict__ E) {
    __shared__ float sEm[DD][256];
    __shared__ float sEn[32][DD];
    __shared__ float srinv[32];
    int t = threadIdx.x;
    int m = blockIdx.x * 256 + t;       // m < KP
    int n0 = blockIdx.y * 32;           // n < KP
    bool mv = (m < NN);
#pragma unroll
    for (int d = 0; d < DD; d++) sEm[d][t] = mv ? g_et[d * NN + m] : 0.f;
    for (int idx = t; idx < 32 * DD; idx += 256) {
        int ni = idx / DD, d = idx % DD;
        sEn[ni][d] = (n0 + ni < NN) ? E[(n0 + ni) * DD + d] : 0.f;
    }
    if (t < 32) srinv[t] = (n0 + t < NN) ? g_rinv[n0 + t] : 0.f;
    __syncthreads();
    for (int ni = 0; ni < 32; ni++) {
        int n = n0 + ni;
        float v = 0.f;
        if (mv && n < NN) {
            float dot = 0.f;
#pragma unroll
            for (int d = 0; d < DD; d++) dot += sEn[ni][d] * sEm[d][t];
            v = __expf(fmaxf(dot, 0.f)) * srinv[ni];
        }
        g_sh[(size_t)n * KP + m] = __float2half_rn(v);
    }
}

// x (B,N,C) -> fp16 [j][k], j=b*64+c, padded K
__global__ void k_conv_b(const float* __restrict__ x) {
    __shared__ float sx[64][65];
    int t = threadIdx.x;
    int j0 = blockIdx.x * 64;
    int k0 = blockIdx.y * 64;
    int b = j0 >> 6;
    for (int idx = t; idx < 4096; idx += 256) {
        int ky = idx >> 6, c = idx & 63;
        int k = k0 + ky;
        sx[ky][c] = (k < NN) ? x[((size_t)b * NN + k) * CC + c] : 0.f;
    }
    __syncthreads();
    for (int idx = t; idx < 4096; idx += 256) {
        int c = idx >> 6, ky = idx & 63;
        g_xh[(size_t)(j0 + c) * KP + k0 + ky] = __float2half_rn(sx[ky][c]);
    }
}

// ================= mma.sync GEMM (single-pass fp16) =================
// Y1[m][j] = sum_k support[m][k] * X[j][k]
// 256x128 CTA tile, 8 warps in 4(m)x2(n), warp tile 64x64, BK=32,
// 4-stage cp.async ring, fp32 accumulate.
#define BM 256
#define BN 128
#define BK 32
#define ASTRIDE 80                  // 64B data + 16B pad per 32-fp16 row
#define TILE_A (BM * ASTRIDE)       // 20480 B
#define TILE_B (BN * ASTRIDE)       // 10240 B
#define STAGE_SZ (TILE_A + TILE_B)  // 30720 B
#define N_STG 4
#define SMEM_DYN (N_STG * STAGE_SZ) // 122880 B
#define N_KC (KP / BK)              // 160

__device__ __forceinline__ void cp16(uint32_t dst, const void* gsrc) {
    asm volatile("cp.async.cg.shared.global [%0], [%1], 16;\n"
                 :: "r"(dst), "l"(__cvta_generic_to_global(gsrc)));
}
__device__ __forceinline__ void cp_commit() { asm volatile("cp.async.commit_group;\n" ::); }
__device__ __forceinline__ void cp_wait2() { asm volatile("cp.async.wait_group 2;\n" :: : "memory"); }

__device__ __forceinline__ void ldsm4(uint32_t* r, uint32_t addr) {
    asm volatile("ldmatrix.sync.aligned.m8n8.x4.shared.b16 {%0,%1,%2,%3}, [%4];\n"
                 : "=r"(r[0]), "=r"(r[1]), "=r"(r[2]), "=r"(r[3]) : "r"(addr));
}
__device__ __forceinline__ void mma16816(float* d, const uint32_t* a, uint32_t b0, uint32_t b1) {
    asm volatile(
        "mma.sync.aligned.m16n8k16.row.col.f32.f16.f16.f32 "
        "{%0,%1,%2,%3}, {%4,%5,%6,%7}, {%8,%9}, {%0,%1,%2,%3};\n"
        : "+f"(d[0]), "+f"(d[1]), "+f"(d[2]), "+f"(d[3])
        : "r"(a[0]), "r"(a[1]), "r"(a[2]), "r"(a[3]), "r"(b0), "r"(b1));
}

extern __shared__ __align__(128) char dsm[];

__device__ __forceinline__ void load_stage(uint32_t stage, int m0, int j0, int k0, int t) {
#pragma unroll
    for (int p = 0; p < 6; p++) {
        int i = p * 256 + t;        // 0..1535
        if (i < 1024) {             // A: 256 rows x 4 chunks
            int row = i >> 2, c = i & 3;
            cp16(stage + row * ASTRIDE + c * 16,
                 g_sh + (size_t)(m0 + row) * KP + k0 + c * 8);
        } else {                    // B: 128 rows x 4 chunks
            int r = i - 1024;
            int row = r >> 2, c = r & 3;
            cp16(stage + TILE_A + row * ASTRIDE + c * 16,
                 g_xh + (size_t)(j0 + row) * KP + k0 + c * 8);
        }
    }
}

__global__ void __launch_bounds__(256, 1) k_gemm_mma() {
    int t = threadIdx.x;
    int lane = t & 31, w = t >> 5;
    int m0 = blockIdx.y * BM, j0 = blockIdx.x * BN;
    int m0w = (w & 3) * 64;    // warp m-offset within tile
    int n0w = (w >> 2) * 64;   // warp n-offset within tile
    uint32_t sb = (uint32_t)__cvta_generic_to_shared(dsm);

    float acc[4][8][4];
#pragma unroll
    for (int mt = 0; mt < 4; mt++)
#pragma unroll
        for (int nt = 0; nt < 8; nt++)
#pragma unroll
            for (int q = 0; q < 4; q++) acc[mt][nt][q] = 0.f;

    // lane-invariant parts of ldmatrix addresses
    int aRow = m0w + (lane & 7) + ((lane >> 3) & 1) * 8;
    uint32_t aCol = ((lane >> 4) & 1) * 16;
    int bRow = n0w + (lane & 7) + ((lane >> 4) & 1) * 8;
    uint32_t bCol = ((lane >> 3) & 1) * 16;

    // prologue: stages 0..2 hold chunks 0..2
#pragma unroll
    for (int c = 0; c < 3; c++) {
        load_stage(sb + c * STAGE_SZ, m0, j0, c * BK, t);
        cp_commit();
    }

    for (int kc = 0; kc < N_KC; kc++) {
        cp_wait2();        // chunk kc resident
        __syncthreads();   // all warps done reading stage (kc+3)%4

        if (kc + 3 < N_KC)
            load_stage(sb + ((kc + 3) % N_STG) * STAGE_SZ, m0, j0, (kc + 3) * BK, t);
        cp_commit();

        uint32_t st = sb + (kc % N_STG) * STAGE_SZ;
#pragma unroll
        for (int kh = 0; kh < 2; kh++) {
            uint32_t kOff = kh * 32;
            uint32_t a[4][4], b[4][4];
#pragma unroll
            for (int mt = 0; mt < 4; mt++)
                ldsm4(a[mt], st + (aRow + mt * 16) * ASTRIDE + aCol + kOff);
#pragma unroll
            for (int pr = 0; pr < 4; pr++)
                ldsm4(b[pr], st + TILE_A + (bRow + pr * 16) * ASTRIDE + bCol + kOff);
#pragma unroll
            for (int mt = 0; mt < 4; mt++)
#pragma unroll
                for (int nt = 0; nt < 8; nt++) {
                    uint32_t* bp = b[nt >> 1];
                    mma16816(acc[mt][nt], a[mt], bp[(nt & 1) * 2], bp[(nt & 1) * 2 + 1]);
                }
        }
    }

    // epilogue: fragment layout -> g_y1
    int g = lane >> 2, tig = lane & 3;
#pragma unroll
    for (int mt = 0; mt < 4; mt++) {
        int r0 = m0 + m0w + mt * 16 + g;
#pragma unroll
        for (int nt = 0; nt < 8; nt++) {
            int col = j0 + n0w + nt * 8 + tig * 2;
            if (r0 < NN)
                *(float2*)(g_y1 + (size_t)r0 * JJ + col) = make_float2(acc[mt][nt][0], acc[mt][nt][1]);
            if (r0 + 8 < NN)
                *(float2*)(g_y1 + (size_t)(r0 + 8) * JJ + col) = make_float2(acc[mt][nt][2], acc[mt][nt][3]);
        }
    }
}

// ================= per-node epilogue =================
__global__ void __launch_bounds__(256) k_out(const float* __restrict__ x,
                                             const float* __restrict__ E,
                                             const float* __restrict__ pool,
                                             const float* __restrict__ bias_pool,
                                             float* __restrict__ out) {
    __shared__ float sW[64 * 64];
    __shared__ float sA[64 * 64];
    __shared__ float sbias[64];
    __shared__ float se[DD];
    int n = blockIdx.x, t = threadIdx.x;
    if (t < DD) se[t] = E[n * DD + t];
    __syncthreads();
    if (t < 64) {
        float b = 0.f;
#pragma unroll
        for (int d = 0; d < DD; d++) b += se[d] * bias_pool[d * 64 + t];
        sbias[t] = b;
    }
    __syncthreads();
    int ty = t >> 4, tx = t & 15;
    float acc[4][4];
#pragma unroll
    for (int r = 0; r < 4; r++)
#pragma unroll
        for (int c = 0; c < 4; c++) acc[r][c] = sbias[tx * 4 + c];

#pragma unroll
    for (int k = 0; k < 2; k++) {
        __syncthreads();
        for (int idx = t; idx < 4096; idx += 256) {
            int i = idx >> 6, o = idx & 63;
            float w = 0.f;
#pragma unroll
            for (int d = 0; d < DD; d++) w += se[d] * pool[((d * 2 + k) * 64 + i) * 64 + o];
            sW[idx] = w;
        }
        if (k == 0) {
            for (int idx = t; idx < 4096; idx += 256) {
                int b = idx >> 6, c = idx & 63;
                sA[idx] = x[((size_t)b * NN + n) * CC + c];
            }
        } else {
            for (int idx = t; idx < 4096; idx += 256) sA[idx] = g_y1[(size_t)n * JJ + idx];
        }
        __syncthreads();
#pragma unroll 16
        for (int i = 0; i < 64; i++) {
            float a[4], wv[4];
#pragma unroll
            for (int r = 0; r < 4; r++) a[r] = sA[(ty * 4 + r) * 64 + i];
#pragma unroll
            for (int c = 0; c < 4; c++) wv[c] = sW[i * 64 + tx * 4 + c];
#pragma unroll
            for (int r = 0; r < 4; r++)
#pragma unroll
                for (int c = 0; c < 4; c++) acc[r][c] += a[r] * wv[c];
        }
    }
#pragma unroll
    for (int r = 0; r < 4; r++) {
        int b = ty * 4 + r;
        float4 v = make_float4(acc[r][0], acc[r][1], acc[r][2], acc[r][3]);
        *(float4*)(out + ((size_t)b * NN + n) * CC + tx * 4) = v;
    }
}

extern "C" void kernel_launch(void* const* d_in, const int* in_sizes, int n_in,
                              void* d_out, int out_size) {
    const float* x         = (const float*)d_in[0];
    const float* E         = (const float*)d_in[1];
    const float* pool      = (const float*)d_in[2];
    const float* bias_pool = (const float*)d_in[3];
    float* out = (float*)d_out;

    cudaFuncSetAttribute(k_gemm_mma, cudaFuncAttributeMaxDynamicSharedMemorySize, SMEM_DYN);

    k_transpose_e<<<(NN + 255) / 256, 256>>>(E);
    k_rowsum<<<NN, 256>>>();
    k_support<<<dim3(KP / 256, KP / 32), 256>>>(E);
    k_conv_b<<<dim3(JJ / 64, KP / 64), 256>>>(x);
    k_gemm_mma<<<dim3(JJ / BN, KP / BM), 256, SMEM_DYN>>>();
    k_out<<<NN, 256>>>(x, E, pool, bias_pool, out);
}